// round 3
// baseline (speedup 1.0000x reference)
#include <cuda_runtime.h>
#include <cstdint>

#define NUSER 50000
#define NITEM 50000
#define NEDGE 1600000
#define D 64

// ---- Scratch (device globals; allocation is forbidden) ----
__device__ int g_deg_item[NITEM];
__device__ int g_deg_user[NUSER];
__device__ int g_off_item[NITEM];
__device__ int g_off_user[NUSER];
__device__ int g_cur_item[NITEM];
__device__ int g_cur_user[NUSER];
__device__ int g_esrc_item[NEDGE];    // user ids, grouped by dst item
__device__ int g_esrc_user[NEDGE];    // item ids, grouped by dst user
__device__ float g_mean_item[NITEM * D];   // mean of user_feat over in-edges
__device__ float g_mean_user[NUSER * D];   // mean of item_feat over in-edges

// ---- f32x2 packed-FMA helpers ----
__device__ __forceinline__ void ffma2(unsigned long long& d,
                                      unsigned long long a, unsigned long long b) {
    asm("fma.rn.f32x2 %0, %1, %2, %0;" : "+l"(d) : "l"(a), "l"(b));
}
__device__ __forceinline__ unsigned long long pk2(float x) {
    unsigned long long r;
    asm("mov.b64 %0, {%1, %1};" : "=l"(r) : "f"(x));
    return r;
}
__device__ __forceinline__ void unpk(unsigned long long v, float& lo, float& hi) {
    asm("mov.b64 {%0, %1}, %2;" : "=f"(lo), "=f"(hi) : "l"(v));
}

// ---------------------------------------------------------------------------
// Zero the degree counters.
// ---------------------------------------------------------------------------
__global__ void init_kernel() {
    int i = blockIdx.x * blockDim.x + threadIdx.x;
    if (i < NITEM) g_deg_item[i] = 0;
    if (i < NUSER) g_deg_user[i] = 0;
}

// ---------------------------------------------------------------------------
// Degree histogram, 4 edges/thread (int4 loads, 8 independent atomic chains).
// ---------------------------------------------------------------------------
__global__ void hist_kernel(const int* __restrict__ rate_dst,
                            const int* __restrict__ rev_dst) {
    int base = (blockIdx.x * blockDim.x + threadIdx.x) * 4;
    if (base >= NEDGE) return;   // NEDGE % 4 == 0, groups always full
    int4 a = *reinterpret_cast<const int4*>(rate_dst + base);
    int4 b = *reinterpret_cast<const int4*>(rev_dst + base);
    atomicAdd(&g_deg_item[a.x], 1);
    atomicAdd(&g_deg_item[a.y], 1);
    atomicAdd(&g_deg_item[a.z], 1);
    atomicAdd(&g_deg_item[a.w], 1);
    atomicAdd(&g_deg_user[b.x], 1);
    atomicAdd(&g_deg_user[b.y], 1);
    atomicAdd(&g_deg_user[b.z], 1);
    atomicAdd(&g_deg_user[b.w], 1);
}

// ---------------------------------------------------------------------------
// Exclusive prefix sum over the 50K degree bins (2 blocks: item / user).
// ---------------------------------------------------------------------------
__global__ void scan_kernel() {
    const int n = (blockIdx.x == 0) ? NITEM : NUSER;
    const int* deg = (blockIdx.x == 0) ? g_deg_item : g_deg_user;
    int* off = (blockIdx.x == 0) ? g_off_item : g_off_user;
    int* cur = (blockIdx.x == 0) ? g_cur_item : g_cur_user;

    __shared__ int wsum[32];
    __shared__ int carry;
    int tid = threadIdx.x, lane = tid & 31, wid = tid >> 5;
    if (tid == 0) carry = 0;
    __syncthreads();

    for (int base = 0; base < n; base += 1024) {
        int i = base + tid;
        int v = (i < n) ? deg[i] : 0;
        int s = v;
        #pragma unroll
        for (int o = 1; o < 32; o <<= 1) {
            int t = __shfl_up_sync(0xffffffffu, s, o);
            if (lane >= o) s += t;
        }
        if (lane == 31) wsum[wid] = s;
        __syncthreads();
        if (wid == 0) {
            int ws = wsum[lane];
            #pragma unroll
            for (int o = 1; o < 32; o <<= 1) {
                int t = __shfl_up_sync(0xffffffffu, ws, o);
                if (lane >= o) ws += t;
            }
            wsum[lane] = ws;
        }
        __syncthreads();
        int excl = carry + (wid ? wsum[wid - 1] : 0) + s - v;
        if (i < n) { off[i] = excl; cur[i] = excl; }
        __syncthreads();
        if (tid == 0) carry += wsum[31];
        __syncthreads();
    }
}

// ---------------------------------------------------------------------------
// Bin edges by destination, 4 edges/thread per etype (8 atomic chains).
// ---------------------------------------------------------------------------
__global__ void bin_kernel(const int* __restrict__ rate_src, const int* __restrict__ rate_dst,
                           const int* __restrict__ rev_src,  const int* __restrict__ rev_dst) {
    int base = (blockIdx.x * blockDim.x + threadIdx.x) * 4;
    if (base >= NEDGE) return;
    int4 rd = *reinterpret_cast<const int4*>(rate_dst + base);
    int4 rs = *reinterpret_cast<const int4*>(rate_src + base);
    int4 vd = *reinterpret_cast<const int4*>(rev_dst + base);
    int4 vs = *reinterpret_cast<const int4*>(rev_src + base);
    int p0 = atomicAdd(&g_cur_item[rd.x], 1);
    int p1 = atomicAdd(&g_cur_item[rd.y], 1);
    int p2 = atomicAdd(&g_cur_item[rd.z], 1);
    int p3 = atomicAdd(&g_cur_item[rd.w], 1);
    int q0 = atomicAdd(&g_cur_user[vd.x], 1);
    int q1 = atomicAdd(&g_cur_user[vd.y], 1);
    int q2 = atomicAdd(&g_cur_user[vd.z], 1);
    int q3 = atomicAdd(&g_cur_user[vd.w], 1);
    g_esrc_item[p0] = rs.x; g_esrc_item[p1] = rs.y;
    g_esrc_item[p2] = rs.z; g_esrc_item[p3] = rs.w;
    g_esrc_user[q0] = vs.x; g_esrc_user[q1] = vs.y;
    g_esrc_user[q2] = vs.z; g_esrc_user[q3] = vs.w;
}

// ---------------------------------------------------------------------------
// Merged gather segment-mean for BOTH sides. 16 threads per dst node, each
// owns one float4 lane. 4-edge unrolled gather for MLP.
// ---------------------------------------------------------------------------
#define AGG_BLOCKS_PER_SIDE (NITEM * 16 / 256)   // 3125
__global__ void agg_kernel(const float* __restrict__ user_feat,
                           const float* __restrict__ item_feat) {
    int b = blockIdx.x;
    const float* feat;
    const int *esrc, *off, *deg;
    float* mean;
    if (b < AGG_BLOCKS_PER_SIDE) {
        feat = user_feat; esrc = g_esrc_item; off = g_off_item;
        deg = g_deg_item; mean = g_mean_item;
    } else {
        b -= AGG_BLOCKS_PER_SIDE;
        feat = item_feat; esrc = g_esrc_user; off = g_off_user;
        deg = g_deg_user; mean = g_mean_user;
    }
    int t = threadIdx.x;
    int node = b * 16 + (t >> 4);
    int lane = t & 15;
    int dgc = __ldg(deg + node);
    const int* ep = esrc + __ldg(off + node);

    float4 acc = make_float4(0.f, 0.f, 0.f, 0.f);
    int j = 0;
    for (; j + 4 <= dgc; j += 4) {
        int s0 = __ldg(ep + j + 0), s1 = __ldg(ep + j + 1);
        int s2 = __ldg(ep + j + 2), s3 = __ldg(ep + j + 3);
        float4 v0 = *reinterpret_cast<const float4*>(feat + (size_t)s0 * D + lane * 4);
        float4 v1 = *reinterpret_cast<const float4*>(feat + (size_t)s1 * D + lane * 4);
        float4 v2 = *reinterpret_cast<const float4*>(feat + (size_t)s2 * D + lane * 4);
        float4 v3 = *reinterpret_cast<const float4*>(feat + (size_t)s3 * D + lane * 4);
        acc.x += v0.x + v1.x + v2.x + v3.x;
        acc.y += v0.y + v1.y + v2.y + v3.y;
        acc.z += v0.z + v1.z + v2.z + v3.z;
        acc.w += v0.w + v1.w + v2.w + v3.w;
    }
    for (; j < dgc; j++) {
        int s = __ldg(ep + j);
        float4 v = *reinterpret_cast<const float4*>(feat + (size_t)s * D + lane * 4);
        acc.x += v.x; acc.y += v.y; acc.z += v.z; acc.w += v.w;
    }
    float inv = (dgc > 0) ? 1.f / (float)dgc : 0.f;
    acc.x *= inv; acc.y *= inv; acc.z *= inv; acc.w *= inv;
    *reinterpret_cast<float4*>(mean + (size_t)node * D + lane * 4) = acc;
}

// ---------------------------------------------------------------------------
// Merged fused dual-GEMM finalize for BOTH sides, packed f32x2 FFMA.
//   out = feat @ W_loop + mean @ W_et + (deg>0 ? b_et : 0) + h_bias
// 64-row tile, 256 threads, 2 rows x 8 cols per thread.
// ---------------------------------------------------------------------------
#define FIN_BLOCKS_PER_SIDE ((NUSER + 63) / 64)   // 782
__global__ void final_kernel(const float* __restrict__ user_feat,
                             const float* __restrict__ item_feat,
                             const float* __restrict__ W_loop,
                             const float* __restrict__ W_rate,
                             const float* __restrict__ W_rev,
                             const float* __restrict__ b_rate,
                             const float* __restrict__ b_rev,
                             const float* __restrict__ h_bias,
                             float* __restrict__ out) {
    __shared__ float As[64][68];
    __shared__ float Ws[64][68];
    __shared__ float bias_h[64];
    __shared__ float bias_e[64];

    int blk = blockIdx.x;
    const float *A0, *A1, *W1, *bet;
    const int* deg;
    float* outp;
    int row0;
    if (blk < FIN_BLOCKS_PER_SIDE) {
        A0 = user_feat; A1 = g_mean_user; W1 = W_rev; bet = b_rev;
        deg = g_deg_user; outp = out; row0 = blk * 64;
    } else {
        A0 = item_feat; A1 = g_mean_item; W1 = W_rate; bet = b_rate;
        deg = g_deg_item; outp = out + (size_t)NUSER * D;
        row0 = (blk - FIN_BLOCKS_PER_SIDE) * 64;
    }
    const int N = NUSER;   // both sides 50000
    const int tid = threadIdx.x;
    const int tx = tid & 7;        // 8 column groups of 8
    const int ty = tid >> 3;       // 0..31
    const int r0 = ty * 2, r1 = r0 + 1;

    if (tid < 64) bias_h[tid] = h_bias[tid];
    else if (tid < 128) bias_e[tid - 64] = bet[tid - 64];

    unsigned long long acc[2][4];
    #pragma unroll
    for (int r = 0; r < 2; r++)
        #pragma unroll
        for (int c = 0; c < 4; c++) acc[r][c] = 0ull;

    const uint32_t ws_base = (uint32_t)__cvta_generic_to_shared(&Ws[0][0]);

    #pragma unroll
    for (int phase = 0; phase < 2; phase++) {
        const float* A = phase ? A1 : A0;
        const float* W = phase ? W1 : W_loop;
        __syncthreads();
        #pragma unroll
        for (int i = tid; i < 1024; i += 256) {
            int k = i >> 4, c4 = (i & 15) << 2;
            float4 w = *reinterpret_cast<const float4*>(W + k * 64 + c4);
            *reinterpret_cast<float4*>(&Ws[k][c4]) = w;
        }
        #pragma unroll
        for (int i = tid; i < 1024; i += 256) {
            int r = i >> 4, k4 = (i & 15) << 2;
            int gr = row0 + r;
            float4 a = (gr < N) ? *reinterpret_cast<const float4*>(A + (size_t)gr * D + k4)
                                : make_float4(0.f, 0.f, 0.f, 0.f);
            *reinterpret_cast<float4*>(&As[r][k4]) = a;
        }
        __syncthreads();

        #pragma unroll
        for (int k = 0; k < 64; k++) {
            unsigned long long w01, w23, w45, w67;
            uint32_t addr = ws_base + (uint32_t)(k * 68 + tx * 8) * 4u;
            asm volatile("ld.shared.v2.u64 {%0, %1}, [%2];"
                         : "=l"(w01), "=l"(w23) : "r"(addr));
            asm volatile("ld.shared.v2.u64 {%0, %1}, [%2+16];"
                         : "=l"(w45), "=l"(w67) : "r"(addr));
            unsigned long long a0 = pk2(As[r0][k]);
            unsigned long long a1 = pk2(As[r1][k]);
            ffma2(acc[0][0], a0, w01); ffma2(acc[0][1], a0, w23);
            ffma2(acc[0][2], a0, w45); ffma2(acc[0][3], a0, w67);
            ffma2(acc[1][0], a1, w01); ffma2(acc[1][1], a1, w23);
            ffma2(acc[1][2], a1, w45); ffma2(acc[1][3], a1, w67);
        }
    }

    #pragma unroll
    for (int r = 0; r < 2; r++) {
        int gr = row0 + (r ? r1 : r0);
        if (gr < N) {
            float m = (__ldg(deg + gr) > 0) ? 1.f : 0.f;
            float v[8];
            #pragma unroll
            for (int c = 0; c < 4; c++) unpk(acc[r][c], v[2 * c], v[2 * c + 1]);
            #pragma unroll
            for (int c = 0; c < 8; c++)
                v[c] += bias_h[tx * 8 + c] + m * bias_e[tx * 8 + c];
            float* po = outp + (size_t)gr * D + tx * 8;
            *reinterpret_cast<float4*>(po) = make_float4(v[0], v[1], v[2], v[3]);
            *reinterpret_cast<float4*>(po + 4) = make_float4(v[4], v[5], v[6], v[7]);
        }
    }
}

extern "C" void kernel_launch(void* const* d_in, const int* in_sizes, int n_in,
                              void* d_out, int out_size) {
    const float* user_feat = (const float*)d_in[0];
    const float* item_feat = (const float*)d_in[1];
    const int*   rate_src  = (const int*)d_in[2];
    const int*   rate_dst  = (const int*)d_in[3];
    const int*   rev_src   = (const int*)d_in[4];
    const int*   rev_dst   = (const int*)d_in[5];
    const float* W_rate    = (const float*)d_in[6];
    const float* b_rate    = (const float*)d_in[7];
    const float* W_rev     = (const float*)d_in[8];
    const float* b_rev     = (const float*)d_in[9];
    const float* W_loop    = (const float*)d_in[10];
    const float* h_bias    = (const float*)d_in[11];

    float* out = (float*)d_out;

    init_kernel<<<(NUSER + 255) / 256, 256>>>();
    const int egrp = NEDGE / 4;                       // 400000 threads
    hist_kernel<<<(egrp + 255) / 256, 256>>>(rate_dst, rev_dst);
    scan_kernel<<<2, 1024>>>();
    bin_kernel<<<(egrp + 255) / 256, 256>>>(rate_src, rate_dst, rev_src, rev_dst);

    agg_kernel<<<2 * AGG_BLOCKS_PER_SIDE, 256>>>(user_feat, item_feat);

    final_kernel<<<2 * FIN_BLOCKS_PER_SIDE, 256>>>(user_feat, item_feat, W_loop,
                                                   W_rate, W_rev, b_rate, b_rev,
                                                   h_bias, out);
}

// round 4
// speedup vs baseline: 1.2852x; 1.2852x over previous
#include <cuda_runtime.h>
#include <cuda_fp16.h>
#include <cstdint>

#define NUSER 50000
#define NITEM 50000
#define NEDGE 1600000
#define D 64

// ---- Scratch (device globals; allocation is forbidden) ----
__device__ int g_deg_item[NITEM];
__device__ int g_deg_user[NUSER];
__device__ int g_off_item[NITEM];
__device__ int g_off_user[NUSER];
__device__ int g_cur_item[NITEM];
__device__ int g_cur_user[NUSER];
__device__ int g_esrc_item[NEDGE];        // user ids, grouped by dst item
__device__ int g_esrc_user[NEDGE];        // item ids, grouped by dst user
__device__ __half g_uf_h[NUSER * D];      // user_feat in fp16 (gather table)
__device__ __half g_if_h[NITEM * D];      // item_feat in fp16 (gather table)
__device__ float g_mean_item[NITEM * D];  // mean of user_feat over in-edges
__device__ float g_mean_user[NUSER * D];  // mean of item_feat over in-edges

// ---------------------------------------------------------------------------
// Zero the degree counters.
// ---------------------------------------------------------------------------
__global__ void init_kernel() {
    int i = blockIdx.x * blockDim.x + threadIdx.x;
    if (i < NITEM) g_deg_item[i] = 0;
    if (i < NUSER) g_deg_user[i] = 0;
}

// ---------------------------------------------------------------------------
// Convert both fp32 feature tables to fp16 gather tables (float4 -> 4 halves).
// ---------------------------------------------------------------------------
__global__ void conv_kernel(const float* __restrict__ user_feat,
                            const float* __restrict__ item_feat) {
    const int n4 = NUSER * D / 4;          // 800000 per side
    int i = blockIdx.x * blockDim.x + threadIdx.x;
    if (i < n4) {
        float4 v = *reinterpret_cast<const float4*>(user_feat + (size_t)i * 4);
        __half2 lo = __floats2half2_rn(v.x, v.y);
        __half2 hi = __floats2half2_rn(v.z, v.w);
        uint2 p = make_uint2(*reinterpret_cast<uint32_t*>(&lo),
                             *reinterpret_cast<uint32_t*>(&hi));
        *reinterpret_cast<uint2*>(g_uf_h + (size_t)i * 4) = p;
    } else if (i < 2 * n4) {
        int j = i - n4;
        float4 v = *reinterpret_cast<const float4*>(item_feat + (size_t)j * 4);
        __half2 lo = __floats2half2_rn(v.x, v.y);
        __half2 hi = __floats2half2_rn(v.z, v.w);
        uint2 p = make_uint2(*reinterpret_cast<uint32_t*>(&lo),
                             *reinterpret_cast<uint32_t*>(&hi));
        *reinterpret_cast<uint2*>(g_if_h + (size_t)j * 4) = p;
    }
}

// ---------------------------------------------------------------------------
// Degree histogram for both edge types (int atomics, spread addresses).
// ---------------------------------------------------------------------------
__global__ void hist_kernel(const int* __restrict__ rate_dst,
                            const int* __restrict__ rev_dst) {
    int i = blockIdx.x * blockDim.x + threadIdx.x;
    if (i < NEDGE) {
        atomicAdd(&g_deg_item[__ldg(rate_dst + i)], 1);
        atomicAdd(&g_deg_user[__ldg(rev_dst + i)], 1);
    }
}

// ---------------------------------------------------------------------------
// Exclusive prefix sum over the 50K degree bins (2 blocks: item / user).
// ---------------------------------------------------------------------------
__global__ void scan_kernel() {
    const int n = (blockIdx.x == 0) ? NITEM : NUSER;
    const int* deg = (blockIdx.x == 0) ? g_deg_item : g_deg_user;
    int* off = (blockIdx.x == 0) ? g_off_item : g_off_user;
    int* cur = (blockIdx.x == 0) ? g_cur_item : g_cur_user;

    __shared__ int wsum[32];
    __shared__ int carry;
    int tid = threadIdx.x, lane = tid & 31, wid = tid >> 5;
    if (tid == 0) carry = 0;
    __syncthreads();

    for (int base = 0; base < n; base += 1024) {
        int i = base + tid;
        int v = (i < n) ? deg[i] : 0;
        int s = v;
        #pragma unroll
        for (int o = 1; o < 32; o <<= 1) {
            int t = __shfl_up_sync(0xffffffffu, s, o);
            if (lane >= o) s += t;
        }
        if (lane == 31) wsum[wid] = s;
        __syncthreads();
        if (wid == 0) {
            int ws = wsum[lane];
            #pragma unroll
            for (int o = 1; o < 32; o <<= 1) {
                int t = __shfl_up_sync(0xffffffffu, ws, o);
                if (lane >= o) ws += t;
            }
            wsum[lane] = ws;
        }
        __syncthreads();
        int excl = carry + (wid ? wsum[wid - 1] : 0) + s - v;
        if (i < n) { off[i] = excl; cur[i] = excl; }
        __syncthreads();
        if (tid == 0) carry += wsum[31];
        __syncthreads();
    }
}

// ---------------------------------------------------------------------------
// Bin edges by destination: slot = atomic cursor bump, store source id.
// ---------------------------------------------------------------------------
__global__ void bin_kernel(const int* __restrict__ rate_src, const int* __restrict__ rate_dst,
                           const int* __restrict__ rev_src,  const int* __restrict__ rev_dst) {
    int i = blockIdx.x * blockDim.x + threadIdx.x;
    if (i < NEDGE) {
        int p = atomicAdd(&g_cur_item[__ldg(rate_dst + i)], 1);
        g_esrc_item[p] = __ldg(rate_src + i);
        int q = atomicAdd(&g_cur_user[__ldg(rev_dst + i)], 1);
        g_esrc_user[q] = __ldg(rev_src + i);
    }
}

// ---------------------------------------------------------------------------
// Gather-based segment mean over fp16 rows: 16 threads per dst node, each
// owns 4 halves (8B) of the 128B row. Accumulate fp32, write fp32 mean.
// ---------------------------------------------------------------------------
__global__ void agg_kernel(const __half* __restrict__ feat, const int* __restrict__ esrc,
                           const int* __restrict__ off, const int* __restrict__ deg,
                           float* __restrict__ mean) {
    int t = blockIdx.x * blockDim.x + threadIdx.x;
    int g = t >> 4;          // node id (grid sized exactly: nnode*16 threads)
    int lane = t & 15;
    int dgc = __ldg(deg + g);
    int start = __ldg(off + g);
    float4 acc = make_float4(0.f, 0.f, 0.f, 0.f);
    #pragma unroll 4
    for (int j = 0; j < dgc; j++) {
        int s = __ldg(esrc + start + j);
        uint2 p = *reinterpret_cast<const uint2*>(feat + (size_t)s * D + lane * 4);
        __half2 h0 = *reinterpret_cast<__half2*>(&p.x);
        __half2 h1 = *reinterpret_cast<__half2*>(&p.y);
        float2 f0 = __half22float2(h0);
        float2 f1 = __half22float2(h1);
        acc.x += f0.x; acc.y += f0.y; acc.z += f1.x; acc.w += f1.y;
    }
    float inv = (dgc > 0) ? 1.f / (float)dgc : 0.f;
    acc.x *= inv; acc.y *= inv; acc.z *= inv; acc.w *= inv;
    *reinterpret_cast<float4*>(mean + (size_t)g * D + lane * 4) = acc;
}

// ---------------------------------------------------------------------------
// Fused dual GEMM finalize:
//   out = feat @ W_loop + mean @ W_et + (deg>0 ? b_et : 0) + h_bias
// 64-row tile, 4x4 register blocking, two accumulate phases over shared tiles.
// ---------------------------------------------------------------------------
__global__ void final_kernel(const float* __restrict__ A0, const float* __restrict__ W0,
                             const float* __restrict__ A1, const float* __restrict__ W1,
                             const float* __restrict__ bet, const float* __restrict__ hb,
                             const int* __restrict__ deg, float* __restrict__ out, int N) {
    __shared__ float As[64][68];
    __shared__ float Ws[64][68];
    __shared__ float bias_h[64];
    __shared__ float bias_e[64];
    const int tid = threadIdx.x;
    const int tx = tid & 15, ty = tid >> 4;
    const int row0 = blockIdx.x * 64;
    const int rb = ty * 4;

    if (tid < 64) bias_h[tid] = hb[tid];
    else if (tid < 128) bias_e[tid - 64] = bet[tid - 64];

    float4 acc[4];
    #pragma unroll
    for (int i = 0; i < 4; i++) acc[i] = make_float4(0.f, 0.f, 0.f, 0.f);

    #pragma unroll
    for (int phase = 0; phase < 2; phase++) {
        const float* A = phase ? A1 : A0;
        const float* W = phase ? W1 : W0;
        __syncthreads();   // protect shared reuse from previous phase
        #pragma unroll
        for (int i = tid; i < 1024; i += 256) {
            int k = i >> 4, c4 = (i & 15) << 2;
            float4 w = *reinterpret_cast<const float4*>(W + k * 64 + c4);
            *reinterpret_cast<float4*>(&Ws[k][c4]) = w;
        }
        #pragma unroll
        for (int i = tid; i < 1024; i += 256) {
            int r = i >> 4, k4 = (i & 15) << 2;
            int gr = row0 + r;
            float4 a = (gr < N) ? *reinterpret_cast<const float4*>(A + (size_t)gr * D + k4)
                                : make_float4(0.f, 0.f, 0.f, 0.f);
            *reinterpret_cast<float4*>(&As[r][k4]) = a;
        }
        __syncthreads();
        #pragma unroll
        for (int k = 0; k < 64; k++) {
            float4 wv = *reinterpret_cast<const float4*>(&Ws[k][tx * 4]);
            float a0 = As[rb + 0][k], a1 = As[rb + 1][k], a2 = As[rb + 2][k], a3 = As[rb + 3][k];
            acc[0].x += a0 * wv.x; acc[0].y += a0 * wv.y; acc[0].z += a0 * wv.z; acc[0].w += a0 * wv.w;
            acc[1].x += a1 * wv.x; acc[1].y += a1 * wv.y; acc[1].z += a1 * wv.z; acc[1].w += a1 * wv.w;
            acc[2].x += a2 * wv.x; acc[2].y += a2 * wv.y; acc[2].z += a2 * wv.z; acc[2].w += a2 * wv.w;
            acc[3].x += a3 * wv.x; acc[3].y += a3 * wv.y; acc[3].z += a3 * wv.z; acc[3].w += a3 * wv.w;
        }
    }

    #pragma unroll
    for (int i = 0; i < 4; i++) {
        int gr = row0 + rb + i;
        if (gr < N) {
            float m = (__ldg(deg + gr) > 0) ? 1.f : 0.f;
            float4 r = acc[i];
            r.x += bias_h[tx * 4 + 0] + m * bias_e[tx * 4 + 0];
            r.y += bias_h[tx * 4 + 1] + m * bias_e[tx * 4 + 1];
            r.z += bias_h[tx * 4 + 2] + m * bias_e[tx * 4 + 2];
            r.w += bias_h[tx * 4 + 3] + m * bias_e[tx * 4 + 3];
            *reinterpret_cast<float4*>(out + (size_t)gr * D + tx * 4) = r;
        }
    }
}

extern "C" void kernel_launch(void* const* d_in, const int* in_sizes, int n_in,
                              void* d_out, int out_size) {
    const float* user_feat = (const float*)d_in[0];
    const float* item_feat = (const float*)d_in[1];
    const int*   rate_src  = (const int*)d_in[2];
    const int*   rate_dst  = (const int*)d_in[3];
    const int*   rev_src   = (const int*)d_in[4];
    const int*   rev_dst   = (const int*)d_in[5];
    const float* W_rate    = (const float*)d_in[6];
    const float* b_rate    = (const float*)d_in[7];
    const float* W_rev     = (const float*)d_in[8];
    const float* b_rev     = (const float*)d_in[9];
    const float* W_loop    = (const float*)d_in[10];
    const float* h_bias    = (const float*)d_in[11];

    float* out      = (float*)d_out;
    float* out_user = out;
    float* out_item = out + (size_t)NUSER * D;

    int *deg_item, *deg_user, *esrc_item, *esrc_user, *off_item, *off_user;
    float *mean_item, *mean_user;
    __half *uf_h, *if_h;
    cudaGetSymbolAddress((void**)&deg_item, g_deg_item);
    cudaGetSymbolAddress((void**)&deg_user, g_deg_user);
    cudaGetSymbolAddress((void**)&off_item, g_off_item);
    cudaGetSymbolAddress((void**)&off_user, g_off_user);
    cudaGetSymbolAddress((void**)&esrc_item, g_esrc_item);
    cudaGetSymbolAddress((void**)&esrc_user, g_esrc_user);
    cudaGetSymbolAddress((void**)&mean_item, g_mean_item);
    cudaGetSymbolAddress((void**)&mean_user, g_mean_user);
    cudaGetSymbolAddress((void**)&uf_h, g_uf_h);
    cudaGetSymbolAddress((void**)&if_h, g_if_h);

    init_kernel<<<(NUSER + 255) / 256, 256>>>();
    conv_kernel<<<(2 * NUSER * D / 4 + 255) / 256, 256>>>(user_feat, item_feat);
    hist_kernel<<<(NEDGE + 255) / 256, 256>>>(rate_dst, rev_dst);
    scan_kernel<<<2, 1024>>>();
    bin_kernel<<<(NEDGE + 255) / 256, 256>>>(rate_src, rate_dst, rev_src, rev_dst);

    // item side aggregates USER features; user side aggregates ITEM features.
    agg_kernel<<<NITEM * 16 / 256, 256>>>(uf_h, esrc_item, off_item, deg_item, mean_item);
    agg_kernel<<<NUSER * 16 / 256, 256>>>(if_h, esrc_user, off_user, deg_user, mean_user);

    final_kernel<<<(NUSER + 63) / 64, 256>>>(user_feat, W_loop, mean_user, W_rev,
                                             b_rev, h_bias, deg_user, out_user, NUSER);
    final_kernel<<<(NITEM + 63) / 64, 256>>>(item_feat, W_loop, mean_item, W_rate,
                                             b_rate, h_bias, deg_item, out_item, NITEM);
}